// round 13
// baseline (speedup 1.0000x reference)
#include <cuda_runtime.h>
#include <cuda_bf16.h>
#include <cstdint>

// ---------------------------------------------------------------------------
// Problem constants
// ---------------------------------------------------------------------------
#define S_ 2048
#define DIM_ 2048
#define H_ 16
#define NOPE_ 128
#define ROPE_ 64
#define VD_ 128
#define LORA_ 512
#define QKH_ 192            // NOPE + ROPE
#define KVW_ 576            // LORA + ROPE
#define KVP_ 640            // kv padded to multiple of 128
#define NQKV_ 3712          // 3072 (q) + 640 (kv padded)
#define KQK_ 192            // per-head qk dim after reassociation
#define SCALE_ 0.07216878364870323f  // 192^-0.5

// ---------------------------------------------------------------------------
// Scratch
// ---------------------------------------------------------------------------
__device__ __nv_bfloat16 d_xhi[(long)S_ * DIM_],      d_xlo[(long)S_ * DIM_];
__device__ __nv_bfloat16 d_wqhi[(long)3072 * DIM_];                                // hi only
__device__ __nv_bfloat16 d_wkvahi[(long)KVP_ * DIM_], d_wkvalo[(long)KVP_ * DIM_];
__device__ __nv_bfloat16 d_wohi[(long)DIM_ * DIM_],   d_wolo[(long)DIM_ * DIM_];
__device__ __nv_bfloat16 d_wkvbhi[(long)H_ * 256 * LORA_], d_wkvblo[(long)H_ * 256 * LORA_];
__device__ __nv_bfloat16 d_qchi[(long)S_ * NQKV_],    d_qclo[(long)S_ * NQKV_];   // lo used for kv cols only
__device__ __nv_bfloat16 d_keffhi[(long)S_ * LORA_],  d_kefflo[(long)S_ * LORA_]; // normed kv_c
__device__ __nv_bfloat16 d_kfullhi[(long)H_ * S_ * KQK_];                         // [k_nope | k_pe], hi only
__device__ __nv_bfloat16 d_vThi[(long)H_ * VD_ * S_], d_vTlo[(long)H_ * VD_ * S_];
__device__ __nv_bfloat16 d_attnhi[(long)H_ * S_ * S_],d_attnlo[(long)H_ * S_ * S_];
__device__ float         d_o2p[2][(long)S_ * DIM_];   // split-K fp32 partials (steps 7 & 8)
__device__ __nv_bfloat16 d_o2hi[(long)S_ * DIM_],     d_o2lo[(long)S_ * DIM_];

// ---------------------------------------------------------------------------
// Helpers
// ---------------------------------------------------------------------------
__device__ __forceinline__ uint32_t smem_u32(const void* p) {
    uint32_t a;
    asm("{ .reg .u64 t; cvta.to.shared.u64 t, %1; cvt.u32.u64 %0, t; }"
        : "=r"(a) : "l"(p));
    return a;
}

__device__ __forceinline__ void ldsm_x4(uint32_t* r, uint32_t addr) {
    asm volatile("ldmatrix.sync.aligned.m8n8.x4.shared.b16 {%0,%1,%2,%3}, [%4];"
                 : "=r"(r[0]), "=r"(r[1]), "=r"(r[2]), "=r"(r[3]) : "r"(addr));
}
__device__ __forceinline__ void ldsm_x2(uint32_t* r, uint32_t addr) {
    asm volatile("ldmatrix.sync.aligned.m8n8.x2.shared.b16 {%0,%1}, [%2];"
                 : "=r"(r[0]), "=r"(r[1]) : "r"(addr));
}
__device__ __forceinline__ void mma16816(float* c, const uint32_t* a, const uint32_t* b) {
    asm volatile(
        "mma.sync.aligned.m16n8k16.row.col.f32.bf16.bf16.f32 "
        "{%0,%1,%2,%3}, {%4,%5,%6,%7}, {%8,%9}, {%0,%1,%2,%3};"
        : "+f"(c[0]), "+f"(c[1]), "+f"(c[2]), "+f"(c[3])
        : "r"(a[0]), "r"(a[1]), "r"(a[2]), "r"(a[3]), "r"(b[0]), "r"(b[1]));
}

__device__ __forceinline__ void split2(float v, __nv_bfloat16& h, __nv_bfloat16& l) {
    h = __float2bfloat16(v);
    l = __float2bfloat16(v - __bfloat162float(h));
}
__device__ __forceinline__ float rec2(__nv_bfloat16 h, __nv_bfloat16 l) {
    return __bfloat162float(h) + __bfloat162float(l);
}

// ---------------------------------------------------------------------------
// Shared GEMM body (bf16 split precision via mma.sync):
//   C += alpha * A(row0.., K) @ B(bcol0.., K)^T over k-chunks [c0, c1)
//   TERMS==3: Ahi.Bhi + Ahi.Blo + Alo.Bhi ; TERMS==1: Ahi.Bhi
// CTA tile 128x128, K chunk 32, cp.async double buffer.
// ---------------------------------------------------------------------------
#define TILE_B 10240            // 128 * 80
#define STAGE_B 40960           // 4 tiles
#define DSMEM_BYTES 81920       // 2 stages

__device__ __forceinline__ void load_tile32(uint32_t dst,
                                            const __nv_bfloat16* __restrict__ src,
                                            int rbase, int ld, int k0, int tid)
{
#pragma unroll
    for (int t = 0; t < 2; t++) {
        int o = tid + t * 256;          // 0..511 : 128 rows x 4 x 16B
        int row = o >> 2, c = o & 3;
        const void* g = (const void*)(src + (long)(rbase + row) * ld + k0 + c * 8);
        asm volatile("cp.async.cg.shared.global [%0], [%1], 16;"
                     :: "r"(dst + row * 80 + c * 16), "l"(g));
    }
}

template <int TERMS>
__device__ __forceinline__ void tgemm_body(
    const __nv_bfloat16* __restrict__ Ahi, const __nv_bfloat16* __restrict__ Alo, int lda,
    const __nv_bfloat16* __restrict__ Bhi, const __nv_bfloat16* __restrict__ Blo, int ldb,
    float* Cf, __nv_bfloat16* Chi, __nv_bfloat16* Clo, int ldc,
    int row0, int bcol0, int ccol0, int c0, int c1, float alpha)
{
    extern __shared__ char dsm[];
    const uint32_t s0 = smem_u32(dsm);

    const int tid = threadIdx.x;
    const int lane = tid & 31;
    const int wid = tid >> 5;
    const int wm = wid & 1;          // 0..1  (M)
    const int wn = wid >> 1;         // 0..3  (N)

    float acc[4][4][4];
#pragma unroll
    for (int mt = 0; mt < 4; mt++)
#pragma unroll
        for (int nt = 0; nt < 4; nt++)
#pragma unroll
            for (int e = 0; e < 4; e++) acc[mt][nt][e] = 0.f;

    // prologue
    {
        uint32_t sb = s0 + (c0 & 1) * STAGE_B;
        int k0 = c0 << 5;
        load_tile32(sb,              Ahi, row0, lda, k0, tid);
        load_tile32(sb + 2 * TILE_B, Bhi, bcol0, ldb, k0, tid);
        if (TERMS == 3) {
            load_tile32(sb + TILE_B,     Alo, row0, lda, k0, tid);
            load_tile32(sb + 3 * TILE_B, Blo, bcol0, ldb, k0, tid);
        }
        asm volatile("cp.async.commit_group;" ::: "memory");
    }

    const uint32_t a_off = (wm * 64 + (lane & 15)) * 80 + ((lane >> 4) << 4);
    const uint32_t b_off = (wn * 32 + (lane & 7)) * 80 + (((lane >> 3) & 1) << 4);

    for (int i = c0; i < c1; i++) {
        if (i + 1 < c1) {
            uint32_t sb = s0 + ((i + 1) & 1) * STAGE_B;
            int k0 = (i + 1) << 5;
            load_tile32(sb,              Ahi, row0, lda, k0, tid);
            load_tile32(sb + 2 * TILE_B, Bhi, bcol0, ldb, k0, tid);
            if (TERMS == 3) {
                load_tile32(sb + TILE_B,     Alo, row0, lda, k0, tid);
                load_tile32(sb + 3 * TILE_B, Blo, bcol0, ldb, k0, tid);
            }
            asm volatile("cp.async.commit_group;" ::: "memory");
            asm volatile("cp.async.wait_group 1;" ::: "memory");
        } else {
            asm volatile("cp.async.wait_group 0;" ::: "memory");
        }
        __syncthreads();

        const uint32_t sb = s0 + (i & 1) * STAGE_B;
#pragma unroll
        for (int ks = 0; ks < 2; ks++) {
            const uint32_t kb = ks * 32;
            uint32_t bh[4][2], bl[4][2];
#pragma unroll
            for (int nt = 0; nt < 4; nt++) {
                ldsm_x2(bh[nt], sb + 2 * TILE_B + b_off + nt * (8 * 80) + kb);
                if (TERMS == 3)
                    ldsm_x2(bl[nt], sb + 3 * TILE_B + b_off + nt * (8 * 80) + kb);
            }
#pragma unroll
            for (int mt = 0; mt < 4; mt++) {
                uint32_t ah[4], al[4];
                ldsm_x4(ah, sb + a_off + mt * (16 * 80) + kb);
                if (TERMS == 3)
                    ldsm_x4(al, sb + TILE_B + a_off + mt * (16 * 80) + kb);
#pragma unroll
                for (int nt = 0; nt < 4; nt++) {
                    mma16816(acc[mt][nt], ah, bh[nt]);
                    if (TERMS == 3) {
                        mma16816(acc[mt][nt], ah, bl[nt]);
                        mma16816(acc[mt][nt], al, bh[nt]);
                    }
                }
            }
        }
        __syncthreads();
    }

    // epilogue: stage through smem
    float* stage = (float*)dsm;   // pitch 132 f32
#pragma unroll
    for (int mt = 0; mt < 4; mt++) {
        int r = wm * 64 + mt * 16 + (lane >> 2);
#pragma unroll
        for (int nt = 0; nt < 4; nt++) {
            int c = wn * 32 + nt * 8 + (lane & 3) * 2;
            stage[r * 132 + c]           = acc[mt][nt][0] * alpha;
            stage[r * 132 + c + 1]       = acc[mt][nt][1] * alpha;
            stage[(r + 8) * 132 + c]     = acc[mt][nt][2] * alpha;
            stage[(r + 8) * 132 + c + 1] = acc[mt][nt][3] * alpha;
        }
    }
    __syncthreads();

#pragma unroll
    for (int it = 0; it < 16; it++) {
        int g = tid + it * 256;
        int m = g >> 5, cg = (g & 31) * 4;
        float v0 = stage[m * 132 + cg + 0];
        float v1 = stage[m * 132 + cg + 1];
        float v2 = stage[m * 132 + cg + 2];
        float v3 = stage[m * 132 + cg + 3];
        long off = (long)(row0 + m) * ldc + ccol0 + cg;
        if (Cf) {
            float4 v = make_float4(v0, v1, v2, v3);
            *(float4*)(Cf + off) = v;
        }
        if (Chi) {
            __nv_bfloat16 h0, h1, h2, h3, l0, l1, l2, l3;
            split2(v0, h0, l0); split2(v1, h1, l1);
            split2(v2, h2, l2); split2(v3, h3, l3);
            *(__nv_bfloat162*)(Chi + off)     = __nv_bfloat162(h0, h1);
            *(__nv_bfloat162*)(Chi + off + 2) = __nv_bfloat162(h2, h3);
            if (Clo) {
                *(__nv_bfloat162*)(Clo + off)     = __nv_bfloat162(l0, l1);
                *(__nv_bfloat162*)(Clo + off + 2) = __nv_bfloat162(l2, l3);
            }
        }
    }
    __syncthreads();
}

// ---------------------------------------------------------------------------
// Generic GEMM wrapper.
//   causal: 1 = skip tiles bx>by; 2 = Klim = min(K, row0+128)
//   ksplit>0 & splitz==0: bx = K-split index (N==128), Cf += bx*sSplit
//   ksplit>0 & splitz==1: z  = K-split index (Z batch must be 1), Cf += z*sSplit
// ---------------------------------------------------------------------------
template <int TERMS>
__global__ void __launch_bounds__(256, 2)
tgemm(const __nv_bfloat16* __restrict__ Ahi, const __nv_bfloat16* __restrict__ Alo,
      long sA, int lda,
      const __nv_bfloat16* __restrict__ Bhi, const __nv_bfloat16* __restrict__ Blo,
      long sB, int ldb,
      float* Cf, __nv_bfloat16* Chi, __nv_bfloat16* Clo,
      long sC, int ldc,
      int K, float alpha, int causal,
      int ksplit, long sSplit, int splitz)
{
    const int bx = blockIdx.x, by = blockIdx.y, z = blockIdx.z;
    if (causal == 1 && bx > by) return;
    const int row0 = by * 128;
    int bcol0 = bx * 128;
    int Klim = (causal == 2) ? min(K, row0 + 128) : K;
    int kstart = 0, kend = Klim;
    if (ksplit > 0) {
        int ksi = splitz ? z : bx;
        if (!splitz) bcol0 = 0;
        kstart = ksi * ksplit;
        kend = min(Klim, kstart + ksplit);
        if (kstart >= kend) return;
        if (Cf) Cf += (long)ksi * sSplit;
    }

    const __nv_bfloat16* Ah = Ahi + (splitz ? 0 : (long)z * sA);
    const __nv_bfloat16* Bh = Bhi + (splitz ? 0 : (long)z * sB);
    const __nv_bfloat16* Al = (TERMS == 3) ? Alo + (splitz ? 0 : (long)z * sA) : nullptr;
    const __nv_bfloat16* Bl = (TERMS == 3) ? Blo + (splitz ? 0 : (long)z * sB) : nullptr;
    long zoff = splitz ? 0 : (long)z * sC;
    float* cf = Cf ? Cf + zoff : nullptr;
    __nv_bfloat16* chi = Chi ? Chi + zoff : nullptr;
    __nv_bfloat16* clo = Clo ? Clo + zoff : nullptr;

    tgemm_body<TERMS>(Ah, Al, lda, Bh, Bl, ldb, cf, chi, clo, ldc,
                      row0, bcol0, bcol0, kstart >> 5, kend >> 5, alpha);
}

// ---------------------------------------------------------------------------
// Merged projection: grid (29, 16, 1).
//   bx < 24 : q  = x @ wq^T   (1-term, hi only)  -> qc cols bx*128
//   bx >= 24: kv = x @ wkva^T (3-term, hi/lo)    -> qc cols 3072+(bx-24)*128
// ---------------------------------------------------------------------------
__global__ void __launch_bounds__(256, 2)
tgemm_qkv(const __nv_bfloat16* __restrict__ xhi, const __nv_bfloat16* __restrict__ xlo,
          const __nv_bfloat16* __restrict__ wqhi,
          const __nv_bfloat16* __restrict__ wkvahi, const __nv_bfloat16* __restrict__ wkvalo,
          __nv_bfloat16* qchi, __nv_bfloat16* qclo)
{
    const int bx = blockIdx.x, by = blockIdx.y;
    const int row0 = by * 128;
    if (bx < 24) {
        tgemm_body<1>(xhi, nullptr, DIM_, wqhi, nullptr, DIM_,
                      nullptr, qchi, nullptr, NQKV_,
                      row0, bx * 128, bx * 128, 0, DIM_ / 32, 1.f);
    } else {
        int kb = bx - 24;
        tgemm_body<3>(xhi, xlo, DIM_, wkvahi, wkvalo, DIM_,
                      nullptr, qchi, qclo, NQKV_,
                      row0, kb * 128, 3072 + kb * 128, 0, DIM_ / 32, 1.f);
    }
}

// ---------------------------------------------------------------------------
// Fused operand split: one launch covering x, wq(hi), wkva(pad), wo, wkvb.
// Segment boundaries in float4 units.
// ---------------------------------------------------------------------------
#define SEG0 1048576L   // x        : 2048*2048/4
#define SEG1 2621440L   // wq       : +3072*2048/4
#define SEG2 2949120L   // wkva pad : +640*2048/4
#define SEG3 3997696L   // wo       : +2048*2048/4
#define SEG4 4521984L   // wkvb     : +16*256*512/4

__global__ void splitall_kernel(
    const float4* __restrict__ x,    __nv_bfloat162* __restrict__ xhi,  __nv_bfloat162* __restrict__ xlo,
    const float4* __restrict__ wq,   __nv_bfloat162* __restrict__ wqhi,
    const float4* __restrict__ wkva, __nv_bfloat162* __restrict__ wkvahi, __nv_bfloat162* __restrict__ wkvalo,
    const float4* __restrict__ wo,   __nv_bfloat162* __restrict__ wohi, __nv_bfloat162* __restrict__ wolo,
    const float4* __restrict__ wkvb, __nv_bfloat162* __restrict__ wkvbhi, __nv_bfloat162* __restrict__ wkvblo)
{
    long i = (long)blockIdx.x * blockDim.x + threadIdx.x;
    if (i >= SEG4) return;

    float4 v;
    __nv_bfloat162 *hi, *lo;
    long j;
    if (i < SEG0) {
        j = i;           v = x[j];   hi = xhi;   lo = xlo;
    } else if (i < SEG1) {
        j = i - SEG0;    v = wq[j];
        wqhi[2 * j]     = __nv_bfloat162(__float2bfloat16(v.x), __float2bfloat16(v.y));
        wqhi[2 * j + 1] = __nv_bfloat162(__float2bfloat16(v.z), __float2bfloat16(v.w));
        return;
    } else if (i < SEG2) {
        j = i - SEG1;
        long r = j / (DIM_ / 4);
        v = (r < KVW_) ? wkva[j] : make_float4(0.f, 0.f, 0.f, 0.f);
        hi = wkvahi; lo = wkvalo;
    } else if (i < SEG3) {
        j = i - SEG2;    v = wo[j];   hi = wohi;  lo = wolo;
    } else {
        j = i - SEG3;    v = wkvb[j]; hi = wkvbhi; lo = wkvblo;
    }

    __nv_bfloat16 h0, h1, h2, h3, l0, l1, l2, l3;
    split2(v.x, h0, l0); split2(v.y, h1, l1);
    split2(v.z, h2, l2); split2(v.w, h3, l3);
    hi[2 * j]     = __nv_bfloat162(h0, h1);
    hi[2 * j + 1] = __nv_bfloat162(h2, h3);
    lo[2 * j]     = __nv_bfloat162(l0, l1);
    lo[2 * j + 1] = __nv_bfloat162(l2, l3);
}

// o2 = p0 + (row >= 1024 ? p1 : 0), split to hi/lo. (step 7 reduction)
__global__ void o2add_kernel(const float4* __restrict__ a,
                             const float4* __restrict__ b,
                             __nv_bfloat162* __restrict__ hi,
                             __nv_bfloat162* __restrict__ lo)
{
    long i = (long)blockIdx.x * blockDim.x + threadIdx.x;
    long n4 = (long)S_ * DIM_ / 4;
    if (i < n4) {
        long row = i / (DIM_ / 4);
        float4 v = a[i];
        if (row >= 1024) {
            float4 w = b[i];
            v.x += w.x; v.y += w.y; v.z += w.z; v.w += w.w;
        }
        __nv_bfloat16 h0, h1, h2, h3, l0, l1, l2, l3;
        split2(v.x, h0, l0); split2(v.y, h1, l1);
        split2(v.z, h2, l2); split2(v.w, h3, l3);
        hi[2 * i]     = __nv_bfloat162(h0, h1);
        hi[2 * i + 1] = __nv_bfloat162(h2, h3);
        lo[2 * i]     = __nv_bfloat162(l0, l1);
        lo[2 * i + 1] = __nv_bfloat162(l2, l3);
    }
}

// out = p0 + p1 (step 8 split-K reduction, fp32)
__global__ void add2out_kernel(const float4* __restrict__ a,
                               const float4* __restrict__ b,
                               float4* __restrict__ out)
{
    long i = (long)blockIdx.x * blockDim.x + threadIdx.x;
    long n4 = (long)S_ * DIM_ / 4;
    if (i < n4) {
        float4 v = a[i], w = b[i];
        v.x += w.x; v.y += w.y; v.z += w.z; v.w += w.w;
        out[i] = v;
    }
}

// rmsnorm(kv_c) -> keff hi/lo ; rope(k_pe) -> kfull cols 128..191 (hi only);
// rope(q_pe) in place in qchi (hi only).
__global__ void prep_kernel(__nv_bfloat16* __restrict__ qchi,
                            __nv_bfloat16* __restrict__ qclo,
                            const float* __restrict__ cosb,
                            const float* __restrict__ sinb,
                            const float* __restrict__ knw,
                            __nv_bfloat16* __restrict__ keffhi,
                            __nv_bfloat16* __restrict__ kefflo,
                            __nv_bfloat16* __restrict__ kfullhi)
{
    const int s = blockIdx.x;
    const int tid = threadIdx.x;
    __nv_bfloat16* kvhi = qchi + (long)s * NQKV_ + 3072;
    __nv_bfloat16* kvlo = qclo + (long)s * NQKV_ + 3072;
    __shared__ float red[256];

    float ss = 0.f;
    for (int c = tid; c < LORA_; c += 256) {
        float v = rec2(kvhi[c], kvlo[c]);
        ss += v * v;
    }
    red[tid] = ss;
    __syncthreads();
    for (int w = 128; w > 0; w >>= 1) {
        if (tid < w) red[tid] += red[tid + w];
        __syncthreads();
    }
    float r = rsqrtf(red[0] / (float)LORA_ + 1e-6f);
    for (int c = tid; c < LORA_; c += 256) {
        float v = rec2(kvhi[c], kvlo[c]);
        __nv_bfloat16 h, l;
        split2(v * r * knw[c], h, l);
        keffhi[(long)s * LORA_ + c] = h;
        kefflo[(long)s * LORA_ + c] = l;
    }

    const float* cs = cosb + s * (ROPE_ / 2);
    const float* sn = sinb + s * (ROPE_ / 2);

    for (int idx = tid; idx < H_ * 32; idx += 256) {
        int h = idx >> 5, i = idx & 31;
        float x0 = rec2(kvhi[LORA_ + 2 * i], kvlo[LORA_ + 2 * i]);
        float x1 = rec2(kvhi[LORA_ + 2 * i + 1], kvlo[LORA_ + 2 * i + 1]);
        float y0 = x0 * cs[i] - x1 * sn[i];
        float y1 = x0 * sn[i] + x1 * cs[i];
        long base = ((long)h * S_ + s) * KQK_ + NOPE_;
        kfullhi[base + 2 * i]     = __float2bfloat16(y0);
        kfullhi[base + 2 * i + 1] = __float2bfloat16(y1);
    }

    for (int idx = tid; idx < H_ * 32; idx += 256) {
        int h = idx >> 5, i = idx & 31;
        long base = (long)s * NQKV_ + h * QKH_ + NOPE_;
        float x0 = __bfloat162float(qchi[base + 2 * i]);
        float x1 = __bfloat162float(qchi[base + 2 * i + 1]);
        float y0 = x0 * cs[i] - x1 * sn[i];
        float y1 = x0 * sn[i] + x1 * cs[i];
        qchi[base + 2 * i]     = __float2bfloat16(y0);
        qchi[base + 2 * i + 1] = __float2bfloat16(y1);
    }
}

// causal softmax: read scores (bf16 hi only, in attnhi), write attn hi/lo.
__global__ void softmax_kernel(__nv_bfloat16* __restrict__ attnhi,
                               __nv_bfloat16* __restrict__ attnlo)
{
    const int s = blockIdx.x, h = blockIdx.y;
    __nv_bfloat16* ohi = attnhi + ((long)h * S_ + s) * S_;
    __nv_bfloat16* olo = attnlo + ((long)h * S_ + s) * S_;
    const int n = s + 1;
    const int nz = ((s >> 7) + 1) << 7;   // round up to 128
    const int tid = threadIdx.x;
    const int lane = tid & 31, wid = tid >> 5;
    const int c0 = tid * 8;
    __shared__ float wred[8];

    float vals[8];
    float m = -1e30f;
    if (c0 < nz) {
        uint4 hv = *(const uint4*)(ohi + c0);
        const __nv_bfloat162* hp = (const __nv_bfloat162*)&hv;
#pragma unroll
        for (int j = 0; j < 4; j++) {
            float2 hf = __bfloat1622float2(hp[j]);
            vals[2 * j]     = hf.x;
            vals[2 * j + 1] = hf.y;
        }
#pragma unroll
        for (int j = 0; j < 8; j++)
            if (c0 + j < n) m = fmaxf(m, vals[j]);
    }
#pragma unroll
    for (int o = 16; o > 0; o >>= 1)
        m = fmaxf(m, __shfl_xor_sync(0xffffffffu, m, o));
    if (lane == 0) wred[wid] = m;
    __syncthreads();
    m = -1e30f;
#pragma unroll
    for (int w = 0; w < 8; w++) m = fmaxf(m, wred[w]);
    __syncthreads();

    float sum = 0.f;
    if (c0 < nz) {
#pragma unroll
        for (int j = 0; j < 8; j++) {
            float e = (c0 + j < n) ? __expf(vals[j] - m) : 0.f;
            vals[j] = e;
            sum += e;
        }
    }
#pragma unroll
    for (int o = 16; o > 0; o >>= 1)
        sum += __shfl_xor_sync(0xffffffffu, sum, o);
    if (lane == 0) wred[wid] = sum;
    __syncthreads();
    sum = 0.f;
#pragma unroll
    for (int w = 0; w < 8; w++) sum += wred[w];
    float inv = 1.0f / sum;

    if (c0 < nz) {
        __nv_bfloat162 hv[4], lv[4];
#pragma unroll
        for (int j = 0; j < 4; j++) {
            __nv_bfloat16 h0, h1, l0, l1;
            split2(vals[2 * j] * inv, h0, l0);
            split2(vals[2 * j + 1] * inv, h1, l1);
            hv[j] = __nv_bfloat162(h0, h1);
            lv[j] = __nv_bfloat162(l0, l1);
        }
        *(uint4*)(ohi + c0) = *(uint4*)hv;
        *(uint4*)(olo + c0) = *(uint4*)lv;
    }
}

// ---------------------------------------------------------------------------
// Launch
// ---------------------------------------------------------------------------
extern "C" void kernel_launch(void* const* d_in, const int* in_sizes, int n_in,
                              void* d_out, int out_size)
{
    const float* x     = (const float*)d_in[0];
    const float* cosb  = (const float*)d_in[1];
    const float* sinb  = (const float*)d_in[2];
    const float* wq    = (const float*)d_in[3];
    const float* wkv_a = (const float*)d_in[4];
    const float* knw   = (const float*)d_in[5];
    const float* wkv_b = (const float*)d_in[6];
    const float* wo    = (const float*)d_in[7];
    float* out = (float*)d_out;

    cudaFuncSetAttribute(tgemm<3>, cudaFuncAttributeMaxDynamicSharedMemorySize,
                         DSMEM_BYTES);
    cudaFuncSetAttribute(tgemm<1>, cudaFuncAttributeMaxDynamicSharedMemorySize,
                         DSMEM_BYTES);
    cudaFuncSetAttribute(tgemm_qkv, cudaFuncAttributeMaxDynamicSharedMemorySize,
                         DSMEM_BYTES);

    __nv_bfloat16 *xhi,*xlo,*wqhi,*wkvahi,*wkvalo,*wohi,*wolo,*wkvbhi,*wkvblo;
    __nv_bfloat16 *qchi,*qclo,*keffhi,*kefflo,*kfullhi;
    __nv_bfloat16 *vThi,*vTlo,*attnhi,*attnlo,*o2hi,*o2lo;
    float *o2p;
    cudaGetSymbolAddress((void**)&xhi, d_xhi);       cudaGetSymbolAddress((void**)&xlo, d_xlo);
    cudaGetSymbolAddress((void**)&wqhi, d_wqhi);
    cudaGetSymbolAddress((void**)&wkvahi, d_wkvahi); cudaGetSymbolAddress((void**)&wkvalo, d_wkvalo);
    cudaGetSymbolAddress((void**)&wohi, d_wohi);     cudaGetSymbolAddress((void**)&wolo, d_wolo);
    cudaGetSymbolAddress((void**)&wkvbhi, d_wkvbhi); cudaGetSymbolAddress((void**)&wkvblo, d_wkvblo);
    cudaGetSymbolAddress((void**)&qchi, d_qchi);     cudaGetSymbolAddress((void**)&qclo, d_qclo);
    cudaGetSymbolAddress((void**)&keffhi, d_keffhi); cudaGetSymbolAddress((void**)&kefflo, d_kefflo);
    cudaGetSymbolAddress((void**)&kfullhi, d_kfullhi);
    cudaGetSymbolAddress((void**)&vThi, d_vThi);     cudaGetSymbolAddress((void**)&vTlo, d_vTlo);
    cudaGetSymbolAddress((void**)&attnhi, d_attnhi); cudaGetSymbolAddress((void**)&attnlo, d_attnlo);
    cudaGetSymbolAddress((void**)&o2p, d_o2p);
    cudaGetSymbolAddress((void**)&o2hi, d_o2hi);     cudaGetSymbolAddress((void**)&o2lo, d_o2lo);

    // 0. fused operand splits (one launch)
    splitall_kernel<<<(SEG4 + 255) / 256, 256>>>(
        (const float4*)x, (__nv_bfloat162*)xhi, (__nv_bfloat162*)xlo,
        (const float4*)wq, (__nv_bfloat162*)wqhi,
        (const float4*)wkv_a, (__nv_bfloat162*)wkvahi, (__nv_bfloat162*)wkvalo,
        (const float4*)wo, (__nv_bfloat162*)wohi, (__nv_bfloat162*)wolo,
        (const float4*)wkv_b, (__nv_bfloat162*)wkvbhi, (__nv_bfloat162*)wkvblo);

    // 1. merged projection: q (1-term) + kv (3-term) in one launch
    tgemm_qkv<<<dim3(29, 16, 1), 256, DSMEM_BYTES>>>(
        xhi, xlo, wqhi, wkvahi, wkvalo, qchi, qclo);

    // 2. prep: rmsnorm + rope
    prep_kernel<<<S_, 256>>>(qchi, qclo, cosb, sinb, knw,
                             keffhi, kefflo, kfullhi);

    // 3. k_nope[h] = keff @ w_uk[h]^T -> kfull[h] cols 0..127 (1-term, hi out)
    tgemm<1><<<dim3(1, 16, H_), 256, DSMEM_BYTES>>>(
        keffhi, nullptr, 0, LORA_,
        wkvbhi, nullptr, (long)256 * LORA_, LORA_,
        nullptr, kfullhi, nullptr, (long)S_ * KQK_, KQK_, LORA_, 1.f, 0, 0, 0, 0);

    // 4. vT[h] = w_uv[h] @ keff^T  (3-term)
    tgemm<3><<<dim3(16, 1, H_), 256, DSMEM_BYTES>>>(
        wkvbhi + (long)NOPE_ * LORA_, wkvblo + (long)NOPE_ * LORA_,
        (long)256 * LORA_, LORA_,
        keffhi, kefflo, 0, LORA_,
        nullptr, vThi, vTlo, (long)VD_ * S_, S_, LORA_, 1.f, 0, 0, 0, 0);

    // 5. scores[h] = SCALE * q[h](K=192) @ kfull[h]^T (1-term, hi out, causal skip)
    tgemm<1><<<dim3(16, 16, H_), 256, DSMEM_BYTES>>>(
        qchi, nullptr, (long)QKH_, NQKV_,
        kfullhi, nullptr, (long)S_ * KQK_, KQK_,
        nullptr, attnhi, nullptr, (long)S_ * S_, S_, KQK_, SCALE_, 1, 0, 0, 0);

    // 6. softmax: scores hi -> attn hi/lo
    softmax_kernel<<<dim3(S_, H_), 256>>>(attnhi, attnlo);

    // 7. o2 partials = attn[h] @ vT[h]^T  (3-term, diag K, 2-way split-K on bx)
    tgemm<3><<<dim3(2, 16, H_), 256, DSMEM_BYTES>>>(
        attnhi, attnlo, (long)S_ * S_, S_,
        vThi, vTlo, (long)VD_ * S_, S_,
        o2p, nullptr, nullptr, (long)VD_, DIM_, S_, 1.f, 2,
        1024, (long)S_ * DIM_, 0);

    // 7b. o2 = o2p[0] + o2p[1] (rows >= 1024), split to hi/lo
    {
        long n4 = (long)S_ * DIM_ / 4;
        o2add_kernel<<<(n4 + 255) / 256, 256>>>(
            (const float4*)o2p, (const float4*)(o2p + (long)S_ * DIM_),
            (__nv_bfloat162*)o2hi, (__nv_bfloat162*)o2lo);
    }

    // 8. out partials = o2 @ wo^T  (3-term, 2-way split-K on z)
    tgemm<3><<<dim3(16, 16, 2), 256, DSMEM_BYTES>>>(
        o2hi, o2lo, 0, DIM_, wohi, wolo, 0, DIM_,
        o2p, nullptr, nullptr, 0, DIM_, DIM_, 1.f, 0,
        1024, (long)S_ * DIM_, 1);

    // 8b. out = p0 + p1
    {
        long n4 = (long)S_ * DIM_ / 4;
        add2out_kernel<<<(n4 + 255) / 256, 256>>>(
            (const float4*)o2p, (const float4*)(o2p + (long)S_ * DIM_),
            (float4*)out);
    }
}

// round 14
// speedup vs baseline: 1.0292x; 1.0292x over previous
#include <cuda_runtime.h>
#include <cuda_bf16.h>
#include <cstdint>

// ---------------------------------------------------------------------------
// Problem constants
// ---------------------------------------------------------------------------
#define S_ 2048
#define DIM_ 2048
#define H_ 16
#define NOPE_ 128
#define ROPE_ 64
#define VD_ 128
#define LORA_ 512
#define QKH_ 192            // NOPE + ROPE
#define KVW_ 576            // LORA + ROPE
#define KVP_ 640            // kv padded to multiple of 128
#define NQKV_ 3712          // 3072 (q) + 640 (kv padded)
#define KQK_ 192            // per-head qk dim after reassociation
#define SCALE_ 0.07216878364870323f  // 192^-0.5

// ---------------------------------------------------------------------------
// Scratch
// ---------------------------------------------------------------------------
__device__ __nv_bfloat16 d_xhi[(long)S_ * DIM_],      d_xlo[(long)S_ * DIM_];
__device__ __nv_bfloat16 d_wqhi[(long)3072 * DIM_];                                // hi only
__device__ __nv_bfloat16 d_wkvahi[(long)KVP_ * DIM_], d_wkvalo[(long)KVP_ * DIM_];
__device__ __nv_bfloat16 d_wohi[(long)DIM_ * DIM_],   d_wolo[(long)DIM_ * DIM_];
__device__ __nv_bfloat16 d_wkvbhi[(long)H_ * 256 * LORA_], d_wkvblo[(long)H_ * 256 * LORA_];
__device__ __nv_bfloat16 d_qchi[(long)S_ * NQKV_],    d_qclo[(long)S_ * NQKV_];   // lo used for kv cols only
__device__ __nv_bfloat16 d_keffhi[(long)S_ * LORA_],  d_kefflo[(long)S_ * LORA_]; // normed kv_c
__device__ __nv_bfloat16 d_kfullhi[(long)H_ * S_ * KQK_];                         // [k_nope | k_pe], hi only
__device__ __nv_bfloat16 d_vThi[(long)H_ * VD_ * S_], d_vTlo[(long)H_ * VD_ * S_];
__device__ __nv_bfloat16 d_attnhi[(long)H_ * S_ * S_],d_attnlo[(long)H_ * S_ * S_];
__device__ float         d_o2p[2][(long)S_ * DIM_];   // split-K fp32 partials (step 7)
__device__ __nv_bfloat16 d_o2hi[(long)S_ * DIM_],     d_o2lo[(long)S_ * DIM_];

// ---------------------------------------------------------------------------
// Helpers
// ---------------------------------------------------------------------------
__device__ __forceinline__ uint32_t smem_u32(const void* p) {
    uint32_t a;
    asm("{ .reg .u64 t; cvta.to.shared.u64 t, %1; cvt.u32.u64 %0, t; }"
        : "=r"(a) : "l"(p));
    return a;
}

__device__ __forceinline__ void ldsm_x4(uint32_t* r, uint32_t addr) {
    asm volatile("ldmatrix.sync.aligned.m8n8.x4.shared.b16 {%0,%1,%2,%3}, [%4];"
                 : "=r"(r[0]), "=r"(r[1]), "=r"(r[2]), "=r"(r[3]) : "r"(addr));
}
__device__ __forceinline__ void ldsm_x2(uint32_t* r, uint32_t addr) {
    asm volatile("ldmatrix.sync.aligned.m8n8.x2.shared.b16 {%0,%1}, [%2];"
                 : "=r"(r[0]), "=r"(r[1]) : "r"(addr));
}
__device__ __forceinline__ void mma16816(float* c, const uint32_t* a, const uint32_t* b) {
    asm volatile(
        "mma.sync.aligned.m16n8k16.row.col.f32.bf16.bf16.f32 "
        "{%0,%1,%2,%3}, {%4,%5,%6,%7}, {%8,%9}, {%0,%1,%2,%3};"
        : "+f"(c[0]), "+f"(c[1]), "+f"(c[2]), "+f"(c[3])
        : "r"(a[0]), "r"(a[1]), "r"(a[2]), "r"(a[3]), "r"(b[0]), "r"(b[1]));
}

__device__ __forceinline__ void split2(float v, __nv_bfloat16& h, __nv_bfloat16& l) {
    h = __float2bfloat16(v);
    l = __float2bfloat16(v - __bfloat162float(h));
}
__device__ __forceinline__ float rec2(__nv_bfloat16 h, __nv_bfloat16 l) {
    return __bfloat162float(h) + __bfloat162float(l);
}

// ---------------------------------------------------------------------------
// Shared GEMM body (bf16 split precision via mma.sync):
//   C += alpha * A(row0.., K) @ B(bcol0.., K)^T over k-chunks [c0, c1)
//   TERMS==3: Ahi.Bhi + Ahi.Blo + Alo.Bhi  (2-stage pipeline, 4 tiles/stage)
//   TERMS==1: Ahi.Bhi                      (4-stage pipeline, 2 tiles/stage)
// CTA tile 128x128, K chunk 32, cp.async multi-stage double buffer.
// ---------------------------------------------------------------------------
#define TILE_B 10240            // 128 * 80
#define DSMEM_BYTES 81920       // 2x4-tile stages OR 4x2-tile stages

__device__ __forceinline__ void load_tile32(uint32_t dst,
                                            const __nv_bfloat16* __restrict__ src,
                                            int rbase, int ld, int k0, int tid)
{
#pragma unroll
    for (int t = 0; t < 2; t++) {
        int o = tid + t * 256;          // 0..511 : 128 rows x 4 x 16B
        int row = o >> 2, c = o & 3;
        const void* g = (const void*)(src + (long)(rbase + row) * ld + k0 + c * 8);
        asm volatile("cp.async.cg.shared.global [%0], [%1], 16;"
                     :: "r"(dst + row * 80 + c * 16), "l"(g));
    }
}

template <int TERMS>
__device__ __forceinline__ void tgemm_body(
    const __nv_bfloat16* __restrict__ Ahi, const __nv_bfloat16* __restrict__ Alo, int lda,
    const __nv_bfloat16* __restrict__ Bhi, const __nv_bfloat16* __restrict__ Blo, int ldb,
    float* Cf, __nv_bfloat16* Chi, __nv_bfloat16* Clo, int ldc,
    int row0, int bcol0, int ccol0, int c0, int c1, float alpha)
{
    constexpr int NST   = (TERMS == 1) ? 4 : 2;         // pipeline stages
    constexpr int STB   = (TERMS == 1) ? 2 * TILE_B : 4 * TILE_B;  // bytes/stage
    constexpr int BOFF  = (TERMS == 1) ? TILE_B : 2 * TILE_B;      // B-hi offset

    extern __shared__ char dsm[];
    const uint32_t s0 = smem_u32(dsm);

    const int tid = threadIdx.x;
    const int lane = tid & 31;
    const int wid = tid >> 5;
    const int wm = wid & 1;          // 0..1  (M)
    const int wn = wid >> 1;         // 0..3  (N)

    float acc[4][4][4];
#pragma unroll
    for (int mt = 0; mt < 4; mt++)
#pragma unroll
        for (int nt = 0; nt < 4; nt++)
#pragma unroll
            for (int e = 0; e < 4; e++) acc[mt][nt][e] = 0.f;

    // prologue: issue NST-1 groups for chunks c0 .. c0+NST-2
#pragma unroll
    for (int s = 0; s < NST - 1; s++) {
        int j = c0 + s;
        if (j < c1) {
            uint32_t sb = s0 + (j & (NST - 1)) * STB;
            int k0 = j << 5;
            load_tile32(sb,        Ahi, row0, lda, k0, tid);
            load_tile32(sb + BOFF, Bhi, bcol0, ldb, k0, tid);
            if (TERMS == 3) {
                load_tile32(sb + TILE_B,     Alo, row0, lda, k0, tid);
                load_tile32(sb + 3 * TILE_B, Blo, bcol0, ldb, k0, tid);
            }
        }
        asm volatile("cp.async.commit_group;" ::: "memory");
    }

    const uint32_t a_off = (wm * 64 + (lane & 15)) * 80 + ((lane >> 4) << 4);
    const uint32_t b_off = (wn * 32 + (lane & 7)) * 80 + (((lane >> 3) & 1) << 4);

    for (int i = c0; i < c1; i++) {
        // issue the group for chunk i+NST-1 (possibly empty), keep counts uniform
        {
            int j = i + NST - 1;
            if (j < c1) {
                uint32_t sb = s0 + (j & (NST - 1)) * STB;
                int k0 = j << 5;
                load_tile32(sb,        Ahi, row0, lda, k0, tid);
                load_tile32(sb + BOFF, Bhi, bcol0, ldb, k0, tid);
                if (TERMS == 3) {
                    load_tile32(sb + TILE_B,     Alo, row0, lda, k0, tid);
                    load_tile32(sb + 3 * TILE_B, Blo, bcol0, ldb, k0, tid);
                }
            }
            asm volatile("cp.async.commit_group;" ::: "memory");
        }
        asm volatile("cp.async.wait_group %0;" :: "n"(NST - 1) : "memory");
        __syncthreads();

        const uint32_t sb = s0 + (i & (NST - 1)) * STB;
#pragma unroll
        for (int ks = 0; ks < 2; ks++) {
            const uint32_t kb = ks * 32;
            uint32_t bh[4][2], bl[4][2];
#pragma unroll
            for (int nt = 0; nt < 4; nt++) {
                ldsm_x2(bh[nt], sb + BOFF + b_off + nt * (8 * 80) + kb);
                if (TERMS == 3)
                    ldsm_x2(bl[nt], sb + 3 * TILE_B + b_off + nt * (8 * 80) + kb);
            }
#pragma unroll
            for (int mt = 0; mt < 4; mt++) {
                uint32_t ah[4], al[4];
                ldsm_x4(ah, sb + a_off + mt * (16 * 80) + kb);
                if (TERMS == 3)
                    ldsm_x4(al, sb + TILE_B + a_off + mt * (16 * 80) + kb);
#pragma unroll
                for (int nt = 0; nt < 4; nt++) {
                    mma16816(acc[mt][nt], ah, bh[nt]);
                    if (TERMS == 3) {
                        mma16816(acc[mt][nt], ah, bl[nt]);
                        mma16816(acc[mt][nt], al, bh[nt]);
                    }
                }
            }
        }
        __syncthreads();
    }

    // epilogue: stage through smem
    float* stage = (float*)dsm;   // pitch 132 f32: 128*132*4 = 67584 <= 81920
#pragma unroll
    for (int mt = 0; mt < 4; mt++) {
        int r = wm * 64 + mt * 16 + (lane >> 2);
#pragma unroll
        for (int nt = 0; nt < 4; nt++) {
            int c = wn * 32 + nt * 8 + (lane & 3) * 2;
            stage[r * 132 + c]           = acc[mt][nt][0] * alpha;
            stage[r * 132 + c + 1]       = acc[mt][nt][1] * alpha;
            stage[(r + 8) * 132 + c]     = acc[mt][nt][2] * alpha;
            stage[(r + 8) * 132 + c + 1] = acc[mt][nt][3] * alpha;
        }
    }
    __syncthreads();

#pragma unroll
    for (int it = 0; it < 16; it++) {
        int g = tid + it * 256;
        int m = g >> 5, cg = (g & 31) * 4;
        float v0 = stage[m * 132 + cg + 0];
        float v1 = stage[m * 132 + cg + 1];
        float v2 = stage[m * 132 + cg + 2];
        float v3 = stage[m * 132 + cg + 3];
        long off = (long)(row0 + m) * ldc + ccol0 + cg;
        if (Cf) {
            float4 v = make_float4(v0, v1, v2, v3);
            *(float4*)(Cf + off) = v;
        }
        if (Chi) {
            __nv_bfloat16 h0, h1, h2, h3, l0, l1, l2, l3;
            split2(v0, h0, l0); split2(v1, h1, l1);
            split2(v2, h2, l2); split2(v3, h3, l3);
            *(__nv_bfloat162*)(Chi + off)     = __nv_bfloat162(h0, h1);
            *(__nv_bfloat162*)(Chi + off + 2) = __nv_bfloat162(h2, h3);
            if (Clo) {
                *(__nv_bfloat162*)(Clo + off)     = __nv_bfloat162(l0, l1);
                *(__nv_bfloat162*)(Clo + off + 2) = __nv_bfloat162(l2, l3);
            }
        }
    }
}

// ---------------------------------------------------------------------------
// Generic GEMM wrapper.
//   causal: 1 = skip tiles bx>by; 2 = Klim = min(K, row0+128)
//   ksplit>0: bx = K-split index (N==128), col0=0, Cf += bx*sSplit
// ---------------------------------------------------------------------------
template <int TERMS>
__global__ void __launch_bounds__(256, 2)
tgemm(const __nv_bfloat16* __restrict__ Ahi, const __nv_bfloat16* __restrict__ Alo,
      long sA, int lda,
      const __nv_bfloat16* __restrict__ Bhi, const __nv_bfloat16* __restrict__ Blo,
      long sB, int ldb,
      float* Cf, __nv_bfloat16* Chi, __nv_bfloat16* Clo,
      long sC, int ldc,
      int K, float alpha, int causal,
      int ksplit, long sSplit)
{
    const int bx = blockIdx.x, by = blockIdx.y, z = blockIdx.z;
    if (causal == 1 && bx > by) return;
    const int row0 = by * 128;
    int bcol0 = bx * 128;
    int Klim = (causal == 2) ? min(K, row0 + 128) : K;
    int kstart = 0, kend = Klim;
    if (ksplit > 0) {
        bcol0 = 0;
        kstart = bx * ksplit;
        kend = min(Klim, kstart + ksplit);
        if (kstart >= kend) return;
        if (Cf) Cf += (long)bx * sSplit;
    }

    const __nv_bfloat16* Ah = Ahi + (long)z * sA;
    const __nv_bfloat16* Bh = Bhi + (long)z * sB;
    const __nv_bfloat16* Al = (TERMS == 3) ? Alo + (long)z * sA : nullptr;
    const __nv_bfloat16* Bl = (TERMS == 3) ? Blo + (long)z * sB : nullptr;
    float* cf = Cf ? Cf + (long)z * sC : nullptr;
    __nv_bfloat16* chi = Chi ? Chi + (long)z * sC : nullptr;
    __nv_bfloat16* clo = Clo ? Clo + (long)z * sC : nullptr;

    tgemm_body<TERMS>(Ah, Al, lda, Bh, Bl, ldb, cf, chi, clo, ldc,
                      row0, bcol0, bcol0, kstart >> 5, kend >> 5, alpha);
}

// ---------------------------------------------------------------------------
// Fused operand split: one launch covering x, wq(hi), wkva(pad), wo, wkvb.
// Segment boundaries in float4 units.
// ---------------------------------------------------------------------------
#define SEG0 1048576L   // x        : 2048*2048/4
#define SEG1 2621440L   // wq       : +3072*2048/4
#define SEG2 2949120L   // wkva pad : +640*2048/4
#define SEG3 3997696L   // wo       : +2048*2048/4
#define SEG4 4521984L   // wkvb     : +16*256*512/4

__global__ void splitall_kernel(
    const float4* __restrict__ x,    __nv_bfloat162* __restrict__ xhi,  __nv_bfloat162* __restrict__ xlo,
    const float4* __restrict__ wq,   __nv_bfloat162* __restrict__ wqhi,
    const float4* __restrict__ wkva, __nv_bfloat162* __restrict__ wkvahi, __nv_bfloat162* __restrict__ wkvalo,
    const float4* __restrict__ wo,   __nv_bfloat162* __restrict__ wohi, __nv_bfloat162* __restrict__ wolo,
    const float4* __restrict__ wkvb, __nv_bfloat162* __restrict__ wkvbhi, __nv_bfloat162* __restrict__ wkvblo)
{
    long i = (long)blockIdx.x * blockDim.x + threadIdx.x;
    if (i >= SEG4) return;

    float4 v;
    __nv_bfloat162 *hi, *lo;
    long j;
    if (i < SEG0) {
        j = i;           v = x[j];   hi = xhi;   lo = xlo;
    } else if (i < SEG1) {
        j = i - SEG0;    v = wq[j];
        wqhi[2 * j]     = __nv_bfloat162(__float2bfloat16(v.x), __float2bfloat16(v.y));
        wqhi[2 * j + 1] = __nv_bfloat162(__float2bfloat16(v.z), __float2bfloat16(v.w));
        return;
    } else if (i < SEG2) {
        j = i - SEG1;
        long r = j / (DIM_ / 4);
        v = (r < KVW_) ? wkva[j] : make_float4(0.f, 0.f, 0.f, 0.f);
        hi = wkvahi; lo = wkvalo;
    } else if (i < SEG3) {
        j = i - SEG2;    v = wo[j];   hi = wohi;  lo = wolo;
    } else {
        j = i - SEG3;    v = wkvb[j]; hi = wkvbhi; lo = wkvblo;
    }

    __nv_bfloat16 h0, h1, h2, h3, l0, l1, l2, l3;
    split2(v.x, h0, l0); split2(v.y, h1, l1);
    split2(v.z, h2, l2); split2(v.w, h3, l3);
    hi[2 * j]     = __nv_bfloat162(h0, h1);
    hi[2 * j + 1] = __nv_bfloat162(h2, h3);
    lo[2 * j]     = __nv_bfloat162(l0, l1);
    lo[2 * j + 1] = __nv_bfloat162(l2, l3);
}

// o2 = p0 + (row >= 1024 ? p1 : 0), split to hi/lo. (step 7 reduction)
__global__ void o2add_kernel(const float4* __restrict__ a,
                             const float4* __restrict__ b,
                             __nv_bfloat162* __restrict__ hi,
                             __nv_bfloat162* __restrict__ lo)
{
    long i = (long)blockIdx.x * blockDim.x + threadIdx.x;
    long n4 = (long)S_ * DIM_ / 4;
    if (i < n4) {
        long row = i / (DIM_ / 4);
        float4 v = a[i];
        if (row >= 1024) {
            float4 w = b[i];
            v.x += w.x; v.y += w.y; v.z += w.z; v.w += w.w;
        }
        __nv_bfloat16 h0, h1, h2, h3, l0, l1, l2, l3;
        split2(v.x, h0, l0); split2(v.y, h1, l1);
        split2(v.z, h2, l2); split2(v.w, h3, l3);
        hi[2 * i]     = __nv_bfloat162(h0, h1);
        hi[2 * i + 1] = __nv_bfloat162(h2, h3);
        lo[2 * i]     = __nv_bfloat162(l0, l1);
        lo[2 * i + 1] = __nv_bfloat162(l2, l3);
    }
}

// rmsnorm(kv_c) -> keff hi/lo ; rope(k_pe) -> kfull cols 128..191 (hi only);
// rope(q_pe) in place in qchi (hi only).
__global__ void prep_kernel(__nv_bfloat16* __restrict__ qchi,
                            __nv_bfloat16* __restrict__ qclo,
                            const float* __restrict__ cosb,
                            const float* __restrict__ sinb,
                            const float* __restrict__ knw,
                            __nv_bfloat16* __restrict__ keffhi,
                            __nv_bfloat16* __restrict__ kefflo,
                            __nv_bfloat16* __restrict__ kfullhi)
{
    const int s = blockIdx.x;
    const int tid = threadIdx.x;
    __nv_bfloat16* kvhi = qchi + (long)s * NQKV_ + 3072;
    __nv_bfloat16* kvlo = qclo + (long)s * NQKV_ + 3072;
    __shared__ float red[256];

    float ss = 0.f;
    for (int c = tid; c < LORA_; c += 256) {
        float v = rec2(kvhi[c], kvlo[c]);
        ss += v * v;
    }
    red[tid] = ss;
    __syncthreads();
    for (int w = 128; w > 0; w >>= 1) {
        if (tid < w) red[tid] += red[tid + w];
        __syncthreads();
    }
    float r = rsqrtf(red[0] / (float)LORA_ + 1e-6f);
    for (int c = tid; c < LORA_; c += 256) {
        float v = rec2(kvhi[c], kvlo[c]);
        __nv_bfloat16 h, l;
        split2(v * r * knw[c], h, l);
        keffhi[(long)s * LORA_ + c] = h;
        kefflo[(long)s * LORA_ + c] = l;
    }

    const float* cs = cosb + s * (ROPE_ / 2);
    const float* sn = sinb + s * (ROPE_ / 2);

    for (int idx = tid; idx < H_ * 32; idx += 256) {
        int h = idx >> 5, i = idx & 31;
        float x0 = rec2(kvhi[LORA_ + 2 * i], kvlo[LORA_ + 2 * i]);
        float x1 = rec2(kvhi[LORA_ + 2 * i + 1], kvlo[LORA_ + 2 * i + 1]);
        float y0 = x0 * cs[i] - x1 * sn[i];
        float y1 = x0 * sn[i] + x1 * cs[i];
        long base = ((long)h * S_ + s) * KQK_ + NOPE_;
        kfullhi[base + 2 * i]     = __float2bfloat16(y0);
        kfullhi[base + 2 * i + 1] = __float2bfloat16(y1);
    }

    for (int idx = tid; idx < H_ * 32; idx += 256) {
        int h = idx >> 5, i = idx & 31;
        long base = (long)s * NQKV_ + h * QKH_ + NOPE_;
        float x0 = __bfloat162float(qchi[base + 2 * i]);
        float x1 = __bfloat162float(qchi[base + 2 * i + 1]);
        float y0 = x0 * cs[i] - x1 * sn[i];
        float y1 = x0 * sn[i] + x1 * cs[i];
        qchi[base + 2 * i]     = __float2bfloat16(y0);
        qchi[base + 2 * i + 1] = __float2bfloat16(y1);
    }
}

// causal softmax: read scores (bf16 hi only, in attnhi), write attn hi/lo.
__global__ void softmax_kernel(__nv_bfloat16* __restrict__ attnhi,
                               __nv_bfloat16* __restrict__ attnlo)
{
    const int s = blockIdx.x, h = blockIdx.y;
    __nv_bfloat16* ohi = attnhi + ((long)h * S_ + s) * S_;
    __nv_bfloat16* olo = attnlo + ((long)h * S_ + s) * S_;
    const int n = s + 1;
    const int nz = ((s >> 7) + 1) << 7;   // round up to 128
    const int tid = threadIdx.x;
    const int lane = tid & 31, wid = tid >> 5;
    const int c0 = tid * 8;
    __shared__ float wred[8];

    float vals[8];
    float m = -1e30f;
    if (c0 < nz) {
        uint4 hv = *(const uint4*)(ohi + c0);
        const __nv_bfloat162* hp = (const __nv_bfloat162*)&hv;
#pragma unroll
        for (int j = 0; j < 4; j++) {
            float2 hf = __bfloat1622float2(hp[j]);
            vals[2 * j]     = hf.x;
            vals[2 * j + 1] = hf.y;
        }
#pragma unroll
        for (int j = 0; j < 8; j++)
            if (c0 + j < n) m = fmaxf(m, vals[j]);
    }
#pragma unroll
    for (int o = 16; o > 0; o >>= 1)
        m = fmaxf(m, __shfl_xor_sync(0xffffffffu, m, o));
    if (lane == 0) wred[wid] = m;
    __syncthreads();
    m = -1e30f;
#pragma unroll
    for (int w = 0; w < 8; w++) m = fmaxf(m, wred[w]);
    __syncthreads();

    float sum = 0.f;
    if (c0 < nz) {
#pragma unroll
        for (int j = 0; j < 8; j++) {
            float e = (c0 + j < n) ? __expf(vals[j] - m) : 0.f;
            vals[j] = e;
            sum += e;
        }
    }
#pragma unroll
    for (int o = 16; o > 0; o >>= 1)
        sum += __shfl_xor_sync(0xffffffffu, sum, o);
    if (lane == 0) wred[wid] = sum;
    __syncthreads();
    sum = 0.f;
#pragma unroll
    for (int w = 0; w < 8; w++) sum += wred[w];
    float inv = 1.0f / sum;

    if (c0 < nz) {
        __nv_bfloat162 hv[4], lv[4];
#pragma unroll
        for (int j = 0; j < 4; j++) {
            __nv_bfloat16 h0, h1, l0, l1;
            split2(vals[2 * j] * inv, h0, l0);
            split2(vals[2 * j + 1] * inv, h1, l1);
            hv[j] = __nv_bfloat162(h0, h1);
            lv[j] = __nv_bfloat162(l0, l1);
        }
        *(uint4*)(ohi + c0) = *(uint4*)hv;
        *(uint4*)(olo + c0) = *(uint4*)lv;
    }
}

// ---------------------------------------------------------------------------
// Launch
// ---------------------------------------------------------------------------
extern "C" void kernel_launch(void* const* d_in, const int* in_sizes, int n_in,
                              void* d_out, int out_size)
{
    const float* x     = (const float*)d_in[0];
    const float* cosb  = (const float*)d_in[1];
    const float* sinb  = (const float*)d_in[2];
    const float* wq    = (const float*)d_in[3];
    const float* wkv_a = (const float*)d_in[4];
    const float* knw   = (const float*)d_in[5];
    const float* wkv_b = (const float*)d_in[6];
    const float* wo    = (const float*)d_in[7];
    float* out = (float*)d_out;

    cudaFuncSetAttribute(tgemm<3>, cudaFuncAttributeMaxDynamicSharedMemorySize,
                         DSMEM_BYTES);
    cudaFuncSetAttribute(tgemm<1>, cudaFuncAttributeMaxDynamicSharedMemorySize,
                         DSMEM_BYTES);

    __nv_bfloat16 *xhi,*xlo,*wqhi,*wkvahi,*wkvalo,*wohi,*wolo,*wkvbhi,*wkvblo;
    __nv_bfloat16 *qchi,*qclo,*keffhi,*kefflo,*kfullhi;
    __nv_bfloat16 *vThi,*vTlo,*attnhi,*attnlo,*o2hi,*o2lo;
    float *o2p;
    cudaGetSymbolAddress((void**)&xhi, d_xhi);       cudaGetSymbolAddress((void**)&xlo, d_xlo);
    cudaGetSymbolAddress((void**)&wqhi, d_wqhi);
    cudaGetSymbolAddress((void**)&wkvahi, d_wkvahi); cudaGetSymbolAddress((void**)&wkvalo, d_wkvalo);
    cudaGetSymbolAddress((void**)&wohi, d_wohi);     cudaGetSymbolAddress((void**)&wolo, d_wolo);
    cudaGetSymbolAddress((void**)&wkvbhi, d_wkvbhi); cudaGetSymbolAddress((void**)&wkvblo, d_wkvblo);
    cudaGetSymbolAddress((void**)&qchi, d_qchi);     cudaGetSymbolAddress((void**)&qclo, d_qclo);
    cudaGetSymbolAddress((void**)&keffhi, d_keffhi); cudaGetSymbolAddress((void**)&kefflo, d_kefflo);
    cudaGetSymbolAddress((void**)&kfullhi, d_kfullhi);
    cudaGetSymbolAddress((void**)&vThi, d_vThi);     cudaGetSymbolAddress((void**)&vTlo, d_vTlo);
    cudaGetSymbolAddress((void**)&attnhi, d_attnhi); cudaGetSymbolAddress((void**)&attnlo, d_attnlo);
    cudaGetSymbolAddress((void**)&o2p, d_o2p);
    cudaGetSymbolAddress((void**)&o2hi, d_o2hi);     cudaGetSymbolAddress((void**)&o2lo, d_o2lo);

    // 0. fused operand splits (one launch)
    splitall_kernel<<<(SEG4 + 255) / 256, 256>>>(
        (const float4*)x, (__nv_bfloat162*)xhi, (__nv_bfloat162*)xlo,
        (const float4*)wq, (__nv_bfloat162*)wqhi,
        (const float4*)wkv_a, (__nv_bfloat162*)wkvahi, (__nv_bfloat162*)wkvalo,
        (const float4*)wo, (__nv_bfloat162*)wohi, (__nv_bfloat162*)wolo,
        (const float4*)wkv_b, (__nv_bfloat162*)wkvbhi, (__nv_bfloat162*)wkvblo);

    // 1a. q = x @ wq^T  (2048 x 3072), 1-term, hi-only output into qc cols 0..3071
    tgemm<1><<<dim3(3072 / 128, 16, 1), 256, DSMEM_BYTES>>>(
        xhi, nullptr, 0, DIM_, wqhi, nullptr, 0, DIM_,
        nullptr, qchi, nullptr, 0, NQKV_, DIM_, 1.f, 0, 0, 0);

    // 1b. kv = x @ wkv_a_pad^T  (2048 x 640), 3-term, hi/lo into qc cols 3072..3711
    tgemm<3><<<dim3(KVP_ / 128, 16, 1), 256, DSMEM_BYTES>>>(
        xhi, xlo, 0, DIM_, wkvahi, wkvalo, 0, DIM_,
        nullptr, qchi + 3072, qclo + 3072, 0, NQKV_, DIM_, 1.f, 0, 0, 0);

    // 2. prep: rmsnorm + rope
    prep_kernel<<<S_, 256>>>(qchi, qclo, cosb, sinb, knw,
                             keffhi, kefflo, kfullhi);

    // 3. k_nope[h] = keff @ w_uk[h]^T -> kfull[h] cols 0..127 (1-term, hi out)
    tgemm<1><<<dim3(1, 16, H_), 256, DSMEM_BYTES>>>(
        keffhi, nullptr, 0, LORA_,
        wkvbhi, nullptr, (long)256 * LORA_, LORA_,
        nullptr, kfullhi, nullptr, (long)S_ * KQK_, KQK_, LORA_, 1.f, 0, 0, 0);

    // 4. vT[h] = w_uv[h] @ keff^T  (3-term)
    tgemm<3><<<dim3(16, 1, H_), 256, DSMEM_BYTES>>>(
        wkvbhi + (long)NOPE_ * LORA_, wkvblo + (long)NOPE_ * LORA_,
        (long)256 * LORA_, LORA_,
        keffhi, kefflo, 0, LORA_,
        nullptr, vThi, vTlo, (long)VD_ * S_, S_, LORA_, 1.f, 0, 0, 0);

    // 5. scores[h] = SCALE * q[h](K=192) @ kfull[h]^T (1-term, hi out, causal skip)
    tgemm<1><<<dim3(16, 16, H_), 256, DSMEM_BYTES>>>(
        qchi, nullptr, (long)QKH_, NQKV_,
        kfullhi, nullptr, (long)S_ * KQK_, KQK_,
        nullptr, attnhi, nullptr, (long)S_ * S_, S_, KQK_, SCALE_, 1, 0, 0);

    // 6. softmax: scores hi -> attn hi/lo
    softmax_kernel<<<dim3(S_, H_), 256>>>(attnhi, attnlo);

    // 7. o2 partials = attn[h] @ vT[h]^T  (3-term, diag K, 2-way split-K, fp32)
    tgemm<3><<<dim3(2, 16, H_), 256, DSMEM_BYTES>>>(
        attnhi, attnlo, (long)S_ * S_, S_,
        vThi, vTlo, (long)VD_ * S_, S_,
        o2p, nullptr, nullptr, (long)VD_, DIM_, S_, 1.f, 2,
        1024, (long)S_ * DIM_);

    // 7b. o2 = o2p[0] + o2p[1] (rows >= 1024), split to hi/lo
    {
        long n4 = (long)S_ * DIM_ / 4;
        o2add_kernel<<<(n4 + 255) / 256, 256>>>(
            (const float4*)o2p, (const float4*)(o2p + (long)S_ * DIM_),
            (__nv_bfloat162*)o2hi, (__nv_bfloat162*)o2lo);
    }

    // 8. out = o2 @ wo^T  (3-term, direct)
    tgemm<3><<<dim3(16, 16, 1), 256, DSMEM_BYTES>>>(
        o2hi, o2lo, 0, DIM_, wohi, wolo, 0, DIM_,
        out, nullptr, nullptr, 0, DIM_, DIM_, 1.f, 0, 0, 0);
}